// round 7
// baseline (speedup 1.0000x reference)
#include <cuda_runtime.h>
#include <cuda_bf16.h>
#include <cstdint>

// BitLevelMapper: B=4194304 rows x 16 bits.
// bits:   [B,16] int32 {0,1}  (d_in[0])
// tables: [16, 32768] float32 {0,1} (d_in[1])
// out:    [B,16] float32
//
// R7: (a) parallel fused pack — one thread per nibble entry, smem combine,
// 137 blocks (was 18 latency-bound blocks, ~6us -> ~2.5us);
// (b) depth-2 software pipeline on the slim R6 map body, occupancy pinned
// at 8 CTAs/SM by __launch_bounds__ so prefetch can't repeat R4's warp loss.

#define NBITS    16
#define TSIZE    32768          // 2^15 entries per table row
// fused words per group: G0(base=12):4096, G1(base=8):256, G2(base=4):16, G3(base=0):1
#define NFWORDS  4369
#define NENTRIES (NFWORDS * 8)  // 34952 nibble entries

__device__ uint32_t g_fused[NFWORDS];

// word offsets of the 4 fused groups (group g has base = 12-4g)
#define OFF_G0 0
#define OFF_G1 4096
#define OFF_G2 4352
#define OFF_G3 4368

// One thread per fused nibble entry; 8 nibbles combined per word in smem.
__global__ void pack_fused_kernel(const float* __restrict__ tables) {
    __shared__ uint32_t s_nib[256];
    int idx = blockIdx.x * blockDim.x + threadIdx.x;
    uint32_t nib = 0;
    int w = idx >> 3;
    if (idx < NENTRIES) {
        int e = idx & 7;
        int base, lw;
        if      (w < OFF_G1) { base = 12; lw = w - OFF_G0; }
        else if (w < OFF_G2) { base = 8;  lw = w - OFF_G1; }
        else if (w < OFF_G3) { base = 4;  lw = w - OFF_G2; }
        else                 { base = 0;  lw = 0; }
        int a = lw * 8 + e;                    // fused entry index (prefix of P)
        #pragma unroll
        for (int k = 0; k < 4; k++) {
            int i = base + k;
            int addr = a & ((1 << i) - 1);     // context address for bit row i
            if (tables[(size_t)i * TSIZE + addr] != 0.0f)
                nib |= 1u << k;
        }
        nib <<= (e * 4);
    }
    s_nib[threadIdx.x] = nib;
    __syncthreads();
    if ((threadIdx.x & 7) == 0 && w < NFWORDS) {
        uint32_t word = 0;
        #pragma unroll
        for (int e = 0; e < 8; e++) word |= s_nib[threadIdx.x + e];
        g_fused[w] = word;
    }
}

#define MAP_BLOCKS  1216        // 152 SMs x 8 CTAs: one full resident wave
#define MAP_THREADS 256

__device__ __forceinline__ float4 quad_out(
    int4 v, int shift, int ibase, unsigned mask, int offq,
    const uint32_t* __restrict__ s_tab)
{
    // partial 16-bit pattern: bit j (array order) sits at position 15-j
    unsigned P = ((unsigned)v.x << shift)       | ((unsigned)v.y << (shift - 1))
               | ((unsigned)v.z << (shift - 2)) | ((unsigned)v.w << (shift - 3));
    // OR-reduce across the aligned 4-lane group -> full pattern in all 4 lanes
    P |= __shfl_xor_sync(0xffffffffu, P, 1);
    P |= __shfl_xor_sync(0xffffffffu, P, 2);

    unsigned addr  = P & mask;                           // prefix of context
    uint32_t wv    = s_tab[offq + (addr >> 3)];
    unsigned flips = (wv >> ((addr & 7u) << 2)) & 0xFu;  // bit k = flip(i=ibase+k)
    unsigned x4    = ((P >> ibase) ^ flips) & 0xFu;      // input ^ flip, 4 bits

    // output column j=4q+m -> bit row i=shift-m -> bit (3-m) of x4
    float4 o;
    o.x = __uint_as_float((0u - ((x4 >> 3) & 1u)) & 0x3f800000u);
    o.y = __uint_as_float((0u - ((x4 >> 2) & 1u)) & 0x3f800000u);
    o.z = __uint_as_float((0u - ((x4 >> 1) & 1u)) & 0x3f800000u);
    o.w = __uint_as_float((0u - ( x4       & 1u)) & 0x3f800000u);
    return o;
}

__global__ void __launch_bounds__(MAP_THREADS, 8)
map_kernel(const int4* __restrict__ bits4, float4* __restrict__ out4, int nquads) {
    __shared__ uint32_t s_tab[NFWORDS];
    for (int t = threadIdx.x; t < NFWORDS; t += blockDim.x)
        s_tab[t] = g_fused[t];
    __syncthreads();

    const int stride = gridDim.x * blockDim.x;
    const int base_t = blockIdx.x * blockDim.x + threadIdx.x;
    const int q      = base_t & 3;          // quarter within row (lane-group pos)
    const int shift  = 15 - 4 * q;          // bit position of v.x in pattern P
    const int ibase  = shift - 3;           // lowest bit row this lane handles
    const unsigned mask = (1u << shift) - 1u;
    const int offq   = (q == 0) ? OFF_G0 : (q == 1) ? OFF_G1
                                         : (q == 2) ? OFF_G2 : OFF_G3;

    const int nmain = nquads / stride;      // uniform across all threads

    if (nmain > 0) {
        int  t = base_t;
        int4 v = bits4[t];                           // pipeline prologue
        for (int it = 1; it < nmain; it++) {
            int4 vn = bits4[t + stride];             // next load in flight
            out4[t] = quad_out(v, shift, ibase, mask, offq, s_tab);
            t += stride;
            v = vn;
        }
        out4[t] = quad_out(v, shift, ibase, mask, offq, s_tab);  // epilogue
    }

    // tail: remaining quads (scalar per-row path, no shuffles; ~1.7% of work)
    for (int t = base_t + nmain * stride; t < nquads; t += stride) {
        int row = t >> 2, qq = t & 3;
        const int4* rp = bits4 + (size_t)row * 4;
        int4 r0 = rp[0], r1 = rp[1], r2 = rp[2], r3 = rp[3];
        int b[16] = { r0.x, r0.y, r0.z, r0.w, r1.x, r1.y, r1.z, r1.w,
                      r2.x, r2.y, r2.z, r2.w, r3.x, r3.y, r3.z, r3.w };
        unsigned P = 0;
        #pragma unroll
        for (int j = 0; j < 16; j++) P |= ((unsigned)b[j] & 1u) << (15 - j);
        int tsh   = 15 - 4 * qq;
        int tbase = tsh - 3;
        unsigned tmask = (1u << tsh) - 1u;
        int toff  = (qq == 0) ? OFF_G0 : (qq == 1) ? OFF_G1
                                       : (qq == 2) ? OFF_G2 : OFF_G3;
        unsigned addr  = P & tmask;
        uint32_t wv    = s_tab[toff + (addr >> 3)];
        unsigned flips = (wv >> ((addr & 7u) << 2)) & 0xFu;
        unsigned x4    = ((P >> tbase) ^ flips) & 0xFu;
        float4 o;
        o.x = __uint_as_float((0u - ((x4 >> 3) & 1u)) & 0x3f800000u);
        o.y = __uint_as_float((0u - ((x4 >> 2) & 1u)) & 0x3f800000u);
        o.z = __uint_as_float((0u - ((x4 >> 1) & 1u)) & 0x3f800000u);
        o.w = __uint_as_float((0u - ( x4       & 1u)) & 0x3f800000u);
        out4[t] = o;
    }
}

extern "C" void kernel_launch(void* const* d_in, const int* in_sizes, int n_in,
                              void* d_out, int out_size) {
    const int4*  bits4  = (const int4*)d_in[0];
    const float* tables = (const float*)d_in[1];
    float4*      out4   = (float4*)d_out;

    int nquads = in_sizes[0] / 4;      // 16777216

    pack_fused_kernel<<<(NENTRIES + 255) / 256, 256>>>(tables);
    map_kernel<<<MAP_BLOCKS, MAP_THREADS>>>(bits4, out4, nquads);
}

// round 8
// speedup vs baseline: 1.0197x; 1.0197x over previous
#include <cuda_runtime.h>
#include <cuda_bf16.h>
#include <cstdint>

// BitLevelMapper: B=4194304 rows x 16 bits.
// bits:   [B,16] int32 {0,1}  (d_in[0])
// tables: [16, 32768] float32 {0,1} (d_in[1])
// out:    [B,16] float32
//
// R8: exact R6 map body (no prefetch — falsified twice) with:
//  (1) tail handled by the same shuffle quad path (the t<nquads predicate is
//      warp-uniform: 278528 % 32 == 0), removing the scalar tail's 4x read
//      amplification (~13MB DRAM);
//  (2) isolated __ldcs/__stcs streaming hints on the zero-reuse in/out.
// Pack: R7 parallel nibble pack (one thread per entry, smem combine).

#define NBITS    16
#define TSIZE    32768          // 2^15 entries per table row
// fused words per group: G0(base=12):4096, G1(base=8):256, G2(base=4):16, G3(base=0):1
#define NFWORDS  4369
#define NENTRIES (NFWORDS * 8)  // 34952 nibble entries

__device__ uint32_t g_fused[NFWORDS];

// word offsets of the 4 fused groups (group g has base = 12-4g)
#define OFF_G0 0
#define OFF_G1 4096
#define OFF_G2 4352
#define OFF_G3 4368

// One thread per fused nibble entry; 8 nibbles combined per word in smem.
__global__ void pack_fused_kernel(const float* __restrict__ tables) {
    __shared__ uint32_t s_nib[256];
    int idx = blockIdx.x * blockDim.x + threadIdx.x;
    uint32_t nib = 0;
    int w = idx >> 3;
    if (idx < NENTRIES) {
        int e = idx & 7;
        int base, lw;
        if      (w < OFF_G1) { base = 12; lw = w - OFF_G0; }
        else if (w < OFF_G2) { base = 8;  lw = w - OFF_G1; }
        else if (w < OFF_G3) { base = 4;  lw = w - OFF_G2; }
        else                 { base = 0;  lw = 0; }
        int a = lw * 8 + e;                    // fused entry index (prefix of P)
        #pragma unroll
        for (int k = 0; k < 4; k++) {
            int i = base + k;
            int addr = a & ((1 << i) - 1);     // context address for bit row i
            if (tables[(size_t)i * TSIZE + addr] != 0.0f)
                nib |= 1u << k;
        }
        nib <<= (e * 4);
    }
    s_nib[threadIdx.x] = nib;
    __syncthreads();
    if ((threadIdx.x & 7) == 0 && w < NFWORDS) {
        uint32_t word = 0;
        #pragma unroll
        for (int e = 0; e < 8; e++) word |= s_nib[threadIdx.x + e];
        g_fused[w] = word;
    }
}

#define MAP_BLOCKS  1216        // 152 SMs x 8 CTAs: one full resident wave
#define MAP_THREADS 256

__global__ void __launch_bounds__(MAP_THREADS, 8)
map_kernel(const int4* __restrict__ bits4, float4* __restrict__ out4, int nquads) {
    __shared__ uint32_t s_tab[NFWORDS];
    for (int t = threadIdx.x; t < NFWORDS; t += blockDim.x)
        s_tab[t] = g_fused[t];
    __syncthreads();

    const int stride = gridDim.x * blockDim.x;
    const int base_t = blockIdx.x * blockDim.x + threadIdx.x;
    const int q      = base_t & 3;          // quarter within row (lane-group pos)
    const int shift  = 15 - 4 * q;          // bit position of v.x in pattern P
    const int ibase  = shift - 3;           // lowest bit row this lane handles
    const unsigned mask = (1u << shift) - 1u;
    const int offq   = (q == 0) ? OFF_G0 : (q == 1) ? OFF_G1
                                         : (q == 2) ? OFF_G2 : OFF_G3;

    const int nmain = nquads / stride;      // uniform across all threads

    // main loop + one residual iteration. The residual predicate t < nquads
    // is warp-uniform because (nquads % stride) is a multiple of 32, so the
    // shuffle quad path is safe there too — no scalar tail, no read amp.
    for (int it = 0; it <= nmain; it++) {
        int t = base_t + it * stride;
        if (t >= nquads) break;             // warp-uniform exit

        int4 v = __ldcs(bits4 + t);

        // partial 16-bit pattern: bit j (array order) sits at position 15-j
        unsigned P = ((unsigned)v.x << shift)       | ((unsigned)v.y << (shift - 1))
                   | ((unsigned)v.z << (shift - 2)) | ((unsigned)v.w << (shift - 3));
        // OR-reduce across the aligned 4-lane group -> full pattern in all 4 lanes
        P |= __shfl_xor_sync(0xffffffffu, P, 1);
        P |= __shfl_xor_sync(0xffffffffu, P, 2);

        unsigned addr  = P & mask;                           // prefix of context
        uint32_t wv    = s_tab[offq + (addr >> 3)];
        unsigned flips = (wv >> ((addr & 7u) << 2)) & 0xFu;  // bit k = flip(i=ibase+k)
        unsigned x4    = ((P >> ibase) ^ flips) & 0xFu;      // input ^ flip, 4 bits

        // output column j=4q+m -> bit row i=shift-m -> bit (3-m) of x4
        float4 o;
        o.x = __uint_as_float((0u - ((x4 >> 3) & 1u)) & 0x3f800000u);
        o.y = __uint_as_float((0u - ((x4 >> 2) & 1u)) & 0x3f800000u);
        o.z = __uint_as_float((0u - ((x4 >> 1) & 1u)) & 0x3f800000u);
        o.w = __uint_as_float((0u - ( x4       & 1u)) & 0x3f800000u);
        __stcs(out4 + t, o);
    }
}

extern "C" void kernel_launch(void* const* d_in, const int* in_sizes, int n_in,
                              void* d_out, int out_size) {
    const int4*  bits4  = (const int4*)d_in[0];
    const float* tables = (const float*)d_in[1];
    float4*      out4   = (float4*)d_out;

    int nquads = in_sizes[0] / 4;      // 16777216

    pack_fused_kernel<<<(NENTRIES + 255) / 256, 256>>>(tables);
    map_kernel<<<MAP_BLOCKS, MAP_THREADS>>>(bits4, out4, nquads);
}

// round 9
// speedup vs baseline: 1.0460x; 1.0258x over previous
#include <cuda_runtime.h>
#include <cuda_bf16.h>
#include <cstdint>

// BitLevelMapper: B=4194304 rows x 16 bits.
// bits:   [B,16] int32 {0,1}  (d_in[0])
// tables: [16, 32768] float32 {0,1} (d_in[1])
// out:    [B,16] float32
//
// R9: best-measured composition.
//  - map body = R5 (packed-bit table, 4 LDS/iter, 32 regs, plain LDG/STG):
//    83.0us, fastest of all bodies tried (fusion/prefetch/.cs all neutral).
//  - pack = R5 ballot pack (cheapest overhead: 7.5us vs fused 10.5-11.5us).
//  - tail = R8 warp-uniform quad path (no scalar 4x re-read; ~13MB DRAM saved).

#define NBITS   16
#define TSIZE   32768           // 2^15 entries per table row
#define NWORDS  2052            // sum over i of ceil(max(2^i,32)/32)

__device__ uint32_t g_packed[NWORDS];

// word offset of table row i in the packed layout
__host__ __device__ __forceinline__ int tab_off(int i) {
    return (i < 5) ? i : ((1 << (i - 5)) + 4);
}

// One warp per packed word: lane b reads entry lw*32+b, ballot packs.
__global__ void pack_tables_kernel(const float* __restrict__ tables) {
    int gw   = (blockIdx.x * blockDim.x + threadIdx.x) >> 5;
    int lane = threadIdx.x & 31;
    if (gw >= NWORDS) return;
    int i = 0;
    #pragma unroll
    for (int r = 1; r < 16; r++)
        if (gw >= tab_off(r)) i = r;
    int lw = gw - tab_off(i);
    float v = tables[(size_t)i * TSIZE + lw * 32 + lane];
    unsigned word = __ballot_sync(0xffffffffu, v != 0.0f);
    if (lane == 0) g_packed[gw] = word;
}

#define MAP_BLOCKS  1216        // 152 SMs x 8 CTAs: one full resident wave
#define MAP_THREADS 256

__global__ void __launch_bounds__(MAP_THREADS, 8)
map_kernel(const int4* __restrict__ bits4, float4* __restrict__ out4, int nquads) {
    __shared__ uint32_t s_tab[NWORDS];
    for (int t = threadIdx.x; t < NWORDS; t += blockDim.x)
        s_tab[t] = g_packed[t];
    __syncthreads();

    const int stride = gridDim.x * blockDim.x;
    const int base_t = blockIdx.x * blockDim.x + threadIdx.x;
    const int q      = base_t & 3;           // quarter within row (lane-group pos)
    const int shift  = 15 - 4 * q;           // bit position of v.x in pattern P

    const int nmain  = nquads / stride;      // uniform across all threads

    // main loop + one residual iteration. The residual predicate t < nquads
    // is warp-uniform ((nquads % stride) is a multiple of 32), so the shuffle
    // quad path is valid in the tail too — no scalar path, no read amp.
    for (int it = 0; it <= nmain; it++) {
        int t = base_t + it * stride;
        if (t >= nquads) break;              // warp-uniform exit

        int4 v = bits4[t];

        // partial 16-bit pattern: bit j (array order) sits at position 15-j
        unsigned P = ((unsigned)v.x << shift)       | ((unsigned)v.y << (shift - 1))
                   | ((unsigned)v.z << (shift - 2)) | ((unsigned)v.w << (shift - 3));
        // OR-reduce across the aligned 4-lane group -> full pattern in all 4 lanes
        P |= __shfl_xor_sync(0xffffffffu, P, 1);
        P |= __shfl_xor_sync(0xffffffffu, P, 2);

        float o[4];
        #pragma unroll
        for (int m = 0; m < 4; m++) {
            int i = shift - m;                             // table row index
            unsigned addr = P & ((1u << i) - 1u);          // prefix of context
            uint32_t wv = s_tab[tab_off(i) + (addr >> 5)];
            unsigned x = ((wv >> (addr & 31u)) ^ (P >> i)) & 1u;   // bit ^ flip
            o[m] = __uint_as_float((0u - x) & 0x3f800000u);        // x ? 1.0f : 0.0f
        }
        out4[t] = make_float4(o[0], o[1], o[2], o[3]);
    }
}

extern "C" void kernel_launch(void* const* d_in, const int* in_sizes, int n_in,
                              void* d_out, int out_size) {
    const int4*  bits4  = (const int4*)d_in[0];
    const float* tables = (const float*)d_in[1];
    float4*      out4   = (float4*)d_out;

    int nquads = in_sizes[0] / 4;      // 16777216

    pack_tables_kernel<<<(NWORDS * 32 + 255) / 256, 256>>>(tables);
    map_kernel<<<MAP_BLOCKS, MAP_THREADS>>>(bits4, out4, nquads);
}

// round 10
// speedup vs baseline: 1.0578x; 1.0113x over previous
#include <cuda_runtime.h>
#include <cuda_bf16.h>
#include <cstdint>

// BitLevelMapper: B=4194304 rows x 16 bits.
// bits:   [B,16] int32 {0,1}  (d_in[0])
// tables: [16, 32768] float32 {0,1} (d_in[1])
// out:    [B,16] float32
//
// R10: R9 (best measured map, 81.7us) + PDL overlap of the pack->map
// serialization. pack triggers programmatic completion right after its
// fenced store; map launches with ProgrammaticStreamSerialization and
// gridDependencySynchronize()s only before touching g_packed, so map's
// launch/CTA-rollout overlaps pack execution.

#define NBITS   16
#define TSIZE   32768           // 2^15 entries per table row
#define NWORDS  2052            // sum over i of ceil(max(2^i,32)/32)

__device__ uint32_t g_packed[NWORDS];

// word offset of table row i in the packed layout
__host__ __device__ __forceinline__ int tab_off(int i) {
    return (i < 5) ? i : ((1 << (i - 5)) + 4);
}

// One warp per packed word: lane b reads entry lw*32+b, ballot packs.
__global__ void pack_tables_kernel(const float* __restrict__ tables) {
    int gw   = (blockIdx.x * blockDim.x + threadIdx.x) >> 5;
    int lane = threadIdx.x & 31;
    if (gw < NWORDS) {
        int i = 0;
        #pragma unroll
        for (int r = 1; r < 16; r++)
            if (gw >= tab_off(r)) i = r;
        int lw = gw - tab_off(i);
        float v = tables[(size_t)i * TSIZE + lw * 32 + lane];
        unsigned word = __ballot_sync(0xffffffffu, v != 0.0f);
        if (lane == 0) g_packed[gw] = word;
    }
    __threadfence();                              // order g_packed before signal
    cudaTriggerProgrammaticLaunchCompletion();    // release dependent launch early
}

#define MAP_BLOCKS  1216        // 152 SMs x 8 CTAs: one full resident wave
#define MAP_THREADS 256

__global__ void __launch_bounds__(MAP_THREADS, 8)
map_kernel(const int4* __restrict__ bits4, float4* __restrict__ out4, int nquads) {
    // Launch/setup overlapped with pack; block only before reading g_packed.
    cudaGridDependencySynchronize();

    __shared__ uint32_t s_tab[NWORDS];
    for (int t = threadIdx.x; t < NWORDS; t += blockDim.x)
        s_tab[t] = g_packed[t];
    __syncthreads();

    const int stride = gridDim.x * blockDim.x;
    const int base_t = blockIdx.x * blockDim.x + threadIdx.x;
    const int q      = base_t & 3;           // quarter within row (lane-group pos)
    const int shift  = 15 - 4 * q;           // bit position of v.x in pattern P

    const int nmain  = nquads / stride;      // uniform across all threads

    // main loop + one residual iteration. The residual predicate t < nquads
    // is warp-uniform ((nquads % stride) is a multiple of 32), so the shuffle
    // quad path is valid in the tail too — no scalar path, no read amp.
    for (int it = 0; it <= nmain; it++) {
        int t = base_t + it * stride;
        if (t >= nquads) break;              // warp-uniform exit

        int4 v = bits4[t];

        // partial 16-bit pattern: bit j (array order) sits at position 15-j
        unsigned P = ((unsigned)v.x << shift)       | ((unsigned)v.y << (shift - 1))
                   | ((unsigned)v.z << (shift - 2)) | ((unsigned)v.w << (shift - 3));
        // OR-reduce across the aligned 4-lane group -> full pattern in all 4 lanes
        P |= __shfl_xor_sync(0xffffffffu, P, 1);
        P |= __shfl_xor_sync(0xffffffffu, P, 2);

        float o[4];
        #pragma unroll
        for (int m = 0; m < 4; m++) {
            int i = shift - m;                             // table row index
            unsigned addr = P & ((1u << i) - 1u);          // prefix of context
            uint32_t wv = s_tab[tab_off(i) + (addr >> 5)];
            unsigned x = ((wv >> (addr & 31u)) ^ (P >> i)) & 1u;   // bit ^ flip
            o[m] = __uint_as_float((0u - x) & 0x3f800000u);        // x ? 1.0f : 0.0f
        }
        out4[t] = make_float4(o[0], o[1], o[2], o[3]);
    }
}

extern "C" void kernel_launch(void* const* d_in, const int* in_sizes, int n_in,
                              void* d_out, int out_size) {
    const int4*  bits4  = (const int4*)d_in[0];
    const float* tables = (const float*)d_in[1];
    float4*      out4   = (float4*)d_out;

    int nquads = in_sizes[0] / 4;      // 16777216

    pack_tables_kernel<<<(NWORDS * 32 + 255) / 256, 256>>>(tables);

    cudaLaunchConfig_t cfg = {};
    cfg.gridDim  = dim3(MAP_BLOCKS, 1, 1);
    cfg.blockDim = dim3(MAP_THREADS, 1, 1);
    cfg.dynamicSmemBytes = 0;
    cfg.stream = 0;                    // legacy default stream (capture target)
    cudaLaunchAttribute attr[1];
    attr[0].id = cudaLaunchAttributeProgrammaticStreamSerialization;
    attr[0].val.programmaticStreamSerializationAllowed = 1;
    cfg.attrs = attr;
    cfg.numAttrs = 1;
    cudaLaunchKernelEx(&cfg, map_kernel, bits4, out4, nquads);
}